// round 11
// baseline (speedup 1.0000x reference)
#include <cuda_runtime.h>
#include <cuda_fp16.h>
#include <math.h>
#include <stdint.h>

#define BATCH   32
#define NHW     64
#define DIM     384
#define HEADS   12
#define HD      32
#define M2      64
#define NWIN    64
#define INNER   384
#define TOK     131072
#define QS      50331648ull

// Scratch
__device__ __half g_xh[(size_t)TOK * DIM];
__device__ __half g_wqh[1152 * 384];
__device__ __half g_woh[384 * 384];
__device__ __half g_qkvh[3ull * QS];
__device__ float  g_bias[HEADS * M2 * M2];
__device__ __half g_attnh[(size_t)TOK * INNER];

// ---------------------------------------------------------------------------
// helpers
// ---------------------------------------------------------------------------
__device__ __forceinline__ void ldm4(unsigned* r, unsigned addr) {
    asm volatile("ldmatrix.sync.aligned.m8n8.x4.shared.b16 {%0,%1,%2,%3}, [%4];"
                 : "=r"(r[0]), "=r"(r[1]), "=r"(r[2]), "=r"(r[3]) : "r"(addr));
}
__device__ __forceinline__ void ldm4t(unsigned* r, unsigned addr) {
    asm volatile("ldmatrix.sync.aligned.m8n8.x4.trans.shared.b16 {%0,%1,%2,%3}, [%4];"
                 : "=r"(r[0]), "=r"(r[1]), "=r"(r[2]), "=r"(r[3]) : "r"(addr));
}
__device__ __forceinline__ void mma16816(float* c, const unsigned* a, unsigned b0, unsigned b1) {
    asm volatile("mma.sync.aligned.m16n8k16.row.col.f32.f16.f16.f32 "
                 "{%0,%1,%2,%3}, {%4,%5,%6,%7}, {%8,%9}, {%0,%1,%2,%3};"
                 : "+f"(c[0]), "+f"(c[1]), "+f"(c[2]), "+f"(c[3])
                 : "r"(a[0]), "r"(a[1]), "r"(a[2]), "r"(a[3]), "r"(b0), "r"(b1));
}
__device__ __forceinline__ void cpa16(unsigned s, const void* g) {
    asm volatile("cp.async.cg.shared.global [%0], [%1], 16;" :: "r"(s), "l"(g));
}

// ---------------------------------------------------------------------------
// shift + convert x -> fp16
// ---------------------------------------------------------------------------
__global__ void __launch_bounds__(256) shiftcvt_x(const float* __restrict__ X) {
    int i4 = blockIdx.x * 256 + threadIdx.x;
    int m = i4 / 96;
    int c = (i4 % 96) * 4;
    int b = m >> 12, H = (m >> 6) & 63, W = m & 63;
    int Hs = (H + 4) & 63, Ws = (W + 4) & 63;
    float4 v = *(const float4*)(X + (size_t)((b << 12) + (Hs << 6) + Ws) * DIM + c);
    __half2 h0 = __floats2half2_rn(v.x, v.y);
    __half2 h1 = __floats2half2_rn(v.z, v.w);
    uint2 out;
    out.x = *(unsigned*)&h0;
    out.y = *(unsigned*)&h1;
    *(uint2*)(g_xh + (size_t)m * DIM + c) = out;
}

__global__ void __launch_bounds__(256) cvt_weights(const float* __restrict__ wq,
                                                   const float* __restrict__ wo) {
    int i = blockIdx.x * 256 + threadIdx.x;
    if (i < 442368) g_wqh[i] = __float2half_rn(wq[i]);
    else if (i < 442368 + 147456) g_woh[i - 442368] = __float2half_rn(wo[i - 442368]);
}

// ---------------------------------------------------------------------------
// CPB-MLP bias
// ---------------------------------------------------------------------------
__global__ void __launch_bounds__(256) cpb_kernel(const float* __restrict__ w1,
                                                  const float* __restrict__ b1,
                                                  const float* __restrict__ w2,
                                                  const float* __restrict__ b2) {
    __shared__ float w1s[1024];
    __shared__ float b1s[512];
    __shared__ float w2s[6144];
    int t = threadIdx.x;
    for (int i = t; i < 1024; i += 256) w1s[i] = w1[i];
    for (int i = t; i < 512;  i += 256) b1s[i] = b1[i];
    for (int i = t; i < 6144; i += 256) w2s[i] = w2[i];
    __syncthreads();

    int idx = blockIdx.x * 256 + t;
    int i = idx >> 6, j = idx & 63;
    float dx = (float)((j >> 3) - (i >> 3));
    float dy = (float)((j & 7) - (i & 7));
    float cx = (dx >= 0.f) ? log1pf(dx) : -log1pf(-dx);
    float cy = (dy >= 0.f) ? log1pf(dy) : -log1pf(-dy);

    float acc[HEADS];
#pragma unroll
    for (int h = 0; h < HEADS; h++) acc[h] = b2[h];
    for (int h0 = 0; h0 < 512; h0++) {
        float hid = fmaxf(cx * w1s[2 * h0] + cy * w1s[2 * h0 + 1] + b1s[h0], 0.f);
#pragma unroll
        for (int h = 0; h < HEADS; h++) acc[h] += hid * w2s[h * 512 + h0];
    }
#pragma unroll
    for (int h = 0; h < HEADS; h++) g_bias[h * 4096 + idx] = acc[h];
}

// ---------------------------------------------------------------------------
// Shared GEMM pieces: 256 thr, CTA 128x128, kc=64, 2-stage (R3 mainloop)
// ---------------------------------------------------------------------------
#define GST 18432
#define QKV_SMEM (4 * GST)
#define OUT_SMEM (4 * GST)

__device__ __forceinline__ void gemm_issue64(unsigned sA, unsigned sB,
                                             const __half* gA, const __half* gB, int t) {
#pragma unroll
    for (int i = 0; i < 4; i++) {
        int idx = i * 256 + t;
        int row = idx >> 3, ch = (idx & 7) * 8;
        cpa16(sA + (row * 72 + ch) * 2, gA + (size_t)row * 384 + ch);
        cpa16(sB + (row * 72 + ch) * 2, gB + (size_t)row * 384 + ch);
    }
    asm volatile("cp.async.commit_group;");
}

__device__ __forceinline__ void gemm_stage64(float acc[4][4][4], unsigned sA, unsigned sB,
                                             int wm, int wn, int lr, int lc) {
#pragma unroll
    for (int ks = 0; ks < 4; ks++) {
        unsigned af[4][4], bf[2][4];
#pragma unroll
        for (int mt = 0; mt < 4; mt++)
            ldm4(af[mt], sA + ((wm * 64 + mt * 16 + lr) * 72 + ks * 16 + lc) * 2);
#pragma unroll
        for (int p = 0; p < 2; p++)
            ldm4(bf[p], sB + ((wn * 32 + p * 16 + lr) * 72 + ks * 16 + lc) * 2);
#pragma unroll
        for (int mt = 0; mt < 4; mt++)
#pragma unroll
            for (int nt = 0; nt < 4; nt++)
                mma16816(acc[mt][nt], af[mt], bf[nt >> 1][nt & 1], bf[nt >> 1][(nt & 1) + 2]);
    }
}

#define GEMM_MAINLOOP(GA, GB)                                                    \
    gemm_issue64(sb + 0 * GST, sb + 2 * GST + 0 * GST, (GA), (GB), t);           \
    for (int it = 0; it < 6; it++) {                                             \
        if (it + 1 < 6) {                                                        \
            int s2 = (it + 1) & 1;                                               \
            gemm_issue64(sb + s2 * GST, sb + 2 * GST + s2 * GST,                 \
                         (GA) + (it + 1) * 64, (GB) + (it + 1) * 64, t);         \
            asm volatile("cp.async.wait_group 1;");                              \
        } else {                                                                 \
            asm volatile("cp.async.wait_group 0;");                              \
        }                                                                        \
        __syncthreads();                                                         \
        int s = it & 1;                                                          \
        gemm_stage64(acc, sb + s * GST, sb + 2 * GST + s * GST, wm, wn, lr, lc); \
        __syncthreads();                                                         \
    }

// ---------------------------------------------------------------------------
// GEMM 1: qkv = g_xh @ g_wqh^T  (M=131072, N=1152, K=384)
// ---------------------------------------------------------------------------
__global__ void __launch_bounds__(256, 2) gemm_qkv_tc() {
    extern __shared__ __align__(16) char dsm[];
    __shared__ unsigned rowoff[128];
    const unsigned sb = (unsigned)__cvta_generic_to_shared(dsm);
    const int t = threadIdx.x;
    const int warp = t >> 5, lane = t & 31;
    const int wm = warp >> 2, wn = warp & 3;
    const int m0 = blockIdx.y * 128, n0 = blockIdx.x * 128;
    const int lr = lane & 15, lc = (lane >> 4) * 8;

    const __half* gA = g_xh + (size_t)m0 * 384;
    const __half* gB = g_wqh + (size_t)n0 * 384;

    float acc[4][4][4];
#pragma unroll
    for (int i = 0; i < 4; i++)
#pragma unroll
        for (int j = 0; j < 4; j++)
#pragma unroll
            for (int k = 0; k < 4; k++) acc[i][j][k] = 0.f;

    GEMM_MAINLOOP(gA, gB)

    // epilogue: stage fp16 tile in smem, coalesced stores via row table
    __half* stg = (__half*)dsm;          // [128][136]
#pragma unroll
    for (int mt = 0; mt < 4; mt++)
#pragma unroll
        for (int nt = 0; nt < 4; nt++)
#pragma unroll
            for (int e = 0; e < 2; e++) {
                int r = wm * 64 + mt * 16 + (lane >> 2) + e * 8;
                int c = wn * 32 + nt * 8 + (lane & 3) * 2;
                *(__half2*)(stg + r * 136 + c) =
                    __floats2half2_rn(acc[mt][nt][e * 2], acc[mt][nt][e * 2 + 1]);
            }
    if (t < 128) {
        int m = m0 + t;
        int b = m >> 12, H = (m >> 6) & 63, W = m & 63;
        int win = ((H >> 3) << 3) + (W >> 3);
        int mm2 = ((H & 7) << 3) + (W & 7);
        rowoff[t] = (unsigned)(b * 1572864 + (win * 64 + mm2) * 32);
    }
    __syncthreads();

    const int qkvi = n0 / 384;
    const int hbase = (n0 % 384) >> 5;
    const __half* gq_base = g_qkvh + (size_t)qkvi * QS;
#pragma unroll
    for (int f = t; f < 2048; f += 256) {
        int ml = f >> 4, q = f & 15;
        int hc = q >> 2, i = q & 3;
        size_t off = (size_t)(hbase + hc) * 131072 + rowoff[ml] + i * 8;
        *(uint4*)((__half*)gq_base + off) = *(const uint4*)(stg + ml * 136 + hc * 32 + i * 8);
    }
}

// ---------------------------------------------------------------------------
// GEMM 2: out = g_attnh @ g_woh^T + b_out (M=131072, N=384, K=384)
// ---------------------------------------------------------------------------
__global__ void __launch_bounds__(256, 2) gemm_out_tc(const float* __restrict__ bo,
                                                      float* __restrict__ OUT) {
    extern __shared__ __align__(16) char dsm[];
    __shared__ unsigned rowoff[128];
    const unsigned sb = (unsigned)__cvta_generic_to_shared(dsm);
    const int t = threadIdx.x;
    const int warp = t >> 5, lane = t & 31;
    const int wm = warp >> 2, wn = warp & 3;
    const int m0 = blockIdx.y * 128, n0 = blockIdx.x * 128;
    const int lr = lane & 15, lc = (lane >> 4) * 8;

    const __half* gA = g_attnh + (size_t)m0 * 384;
    const __half* gB = g_woh + (size_t)n0 * 384;

    float acc[4][4][4];
#pragma unroll
    for (int i = 0; i < 4; i++)
#pragma unroll
        for (int j = 0; j < 4; j++)
#pragma unroll
            for (int k = 0; k < 4; k++) acc[i][j][k] = 0.f;

    GEMM_MAINLOOP(gA, gB)

    float* stg = (float*)dsm;            // [128][132]
#pragma unroll
    for (int mt = 0; mt < 4; mt++)
#pragma unroll
        for (int nt = 0; nt < 4; nt++) {
            int c = wn * 32 + nt * 8 + (lane & 3) * 2;
            float b0 = bo[n0 + c], b1 = bo[n0 + c + 1];
#pragma unroll
            for (int e = 0; e < 2; e++) {
                int r = wm * 64 + mt * 16 + (lane >> 2) + e * 8;
                *(float2*)(stg + r * 132 + c) =
                    make_float2(acc[mt][nt][e * 2] + b0, acc[mt][nt][e * 2 + 1] + b1);
            }
        }
    if (t < 128) {
        int m = m0 + t;
        int b = m >> 12, H = (m >> 6) & 63, W = m & 63;
        int Ho = (H + 4) & 63, Wo = (W + 4) & 63;
        rowoff[t] = (unsigned)(((b << 12) + (Ho << 6) + Wo) * 384);
    }
    __syncthreads();

#pragma unroll
    for (int f = t; f < 4096; f += 256) {
        int ml = f >> 5, c4 = (f & 31) * 4;
        *(float4*)(OUT + rowoff[ml] + n0 + c4) = *(const float4*)(stg + ml * 132 + c4);
    }
}

// ---------------------------------------------------------------------------
// Pipelined tensor-core attention: one CTA (128 thr) per 8 windows (same b,h).
// Double-buffered cp.async prefetch of q/k/v hides the cold-load latency.
// Dynamic smem: buf[2][3][64*40]h (30720B) | sp[64*72]h (9216B) | spf[64*68]f (17408B)
// ---------------------------------------------------------------------------
#define NWPC 8
#define ABUF 15360                    // one qkv buffer, bytes
#define SP_OFF (2 * ABUF)             // 30720
#define SPF_OFF (SP_OFF + 9216)      // 39936
#define ATTN_SMEM (SPF_OFF + 17408)  // 57344

__device__ __forceinline__ void attn_prefetch(unsigned buf, const __half* gq,
                                              const __half* gk, const __half* gv, int t) {
    for (int f = t; f < 256; f += 128) {
        int row = f >> 2, ch = (f & 3) * 8;
        cpa16(buf + (row * 40 + ch) * 2, gq + row * 32 + ch);
        cpa16(buf + 5120 + (row * 40 + ch) * 2, gk + row * 32 + ch);
        cpa16(buf + 10240 + (row * 40 + ch) * 2, gv + row * 32 + ch);
    }
    asm volatile("cp.async.commit_group;");
}

__global__ void __launch_bounds__(128) attn_tc(const float* __restrict__ tau,
                                               float* __restrict__ attn_out) {
    extern __shared__ __align__(16) char asm_[];
    const unsigned sbase = (unsigned)__cvta_generic_to_shared(asm_);
    __half* smh = (__half*)asm_;

    const int g0 = blockIdx.x * NWPC;
    const int w0 = g0 & 63;
    const int h = (g0 >> 6) % HEADS;
    const int b = g0 / (HEADS * NWIN);
    const int t = threadIdx.x;
    const int lane = t & 31, warp = t >> 5;

    const size_t base0 = ((size_t)(b * HEADS + h) * NWIN + w0) * 2048;
    const __half* gq0 = g_qkvh + base0;
    const __half* gk0 = g_qkvh + QS + base0;
    const __half* gv0 = g_qkvh + 2ull * QS + base0;

    const float invtau = 1.0f / fmaxf(tau[h], 0.01f);
    const float* bb = g_bias + h * 4096;
    const int lr = lane & 15, lc = (lane >> 4) * 8;
    const int i0 = warp * 16;
    const int r0 = i0 + (lane >> 2);
    const int r1 = r0 + 8;
    const int jb = (lane & 3) * 2;
    const bool i0ge = (r0 >= 32), i1ge = (r1 >= 32);
    const bool ih = ((r0 & 7) >= 4);

    __half* sp  = smh + SP_OFF / 2;          // [64][72] fp16 probs
    float*  spf = (float*)(asm_ + SPF_OFF);  // [64][68] fp32 probs / O staging
    const unsigned spa  = sbase + SP_OFF;

    attn_prefetch(sbase, gq0, gk0, gv0, t);

    for (int wi = 0; wi < NWPC; wi++) {
        const int w = w0 + wi;
        const unsigned buf = sbase + (wi & 1) * ABUF;
        __half* sq = (__half*)(asm_ + (wi & 1) * ABUF);
        __half* sk = sq + 2560;

        if (wi + 1 < NWPC) {
            attn_prefetch(sbase + ((wi + 1) & 1) * ABUF,
                          gq0 + (wi + 1) * 2048, gk0 + (wi + 1) * 2048,
                          gv0 + (wi + 1) * 2048, t);
            asm volatile("cp.async.wait_group 1;");
        } else {
            asm volatile("cp.async.wait_group 0;");
        }
        __syncthreads();

        // L2-normalize q,k rows
        {
            __half* rowp = ((t < 64) ? sq : sk) + (t & 63) * 40;
            float vals[32];
            float ss = 0.f;
#pragma unroll
            for (int i = 0; i < 16; i++) {
                float2 v2 = __half22float2(*(__half2*)(rowp + 2 * i));
                vals[2 * i] = v2.x; vals[2 * i + 1] = v2.y;
                ss += v2.x * v2.x + v2.y * v2.y;
            }
            float sc = 1.f / fmaxf(sqrtf(ss), 1e-12f);
#pragma unroll
            for (int i = 0; i < 16; i++)
                *(__half2*)(rowp + 2 * i) = __floats2half2_rn(vals[2 * i] * sc, vals[2 * i + 1] * sc);
        }
        __syncthreads();

        // S = q @ k^T
        float s_acc[8][4];
#pragma unroll
        for (int nt = 0; nt < 8; nt++)
#pragma unroll
            for (int c = 0; c < 4; c++) s_acc[nt][c] = 0.f;

#pragma unroll
        for (int ks = 0; ks < 2; ks++) {
            unsigned af[4], bf[4][4];
            ldm4(af, buf + ((i0 + lr) * 40 + ks * 16 + lc) * 2);
#pragma unroll
            for (int p = 0; p < 4; p++)
                ldm4(bf[p], buf + 5120 + ((p * 16 + lr) * 40 + ks * 16 + lc) * 2);
#pragma unroll
            for (int nt = 0; nt < 8; nt++)
                mma16816(s_acc[nt], af, bf[nt >> 1][nt & 1], bf[nt >> 1][(nt & 1) + 2]);
        }

        // softmax
        const bool ulm = (w >= 56);
        const bool lrm = ((w & 7) == 7);
        float mx0 = -1e38f, mx1 = -1e38f;
#pragma unroll
        for (int nt = 0; nt < 8; nt++) {
            int j = nt * 8 + jb;
            bool jge = (j >= 32), jh = ((j & 7) >= 4);
            float2 bv0 = *(const float2*)(bb + r0 * 64 + j);
            float2 bv1 = *(const float2*)(bb + r1 * 64 + j);
            float m0a = ((ulm && (i0ge != jge)) || (lrm && (ih != jh))) ? -1e30f : 0.f;
            float m1a = ((ulm && (i1ge != jge)) || (lrm && (ih != jh))) ? -1e30f : 0.f;
            s_acc[nt][0] = s_acc[nt][0] * invtau + bv0.x + m0a;
            s_acc[nt][1] = s_acc[nt][1] * invtau + bv0.y + m0a;
            s_acc[nt][2] = s_acc[nt][2] * invtau + bv1.x + m1a;
            s_acc[nt][3] = s_acc[nt][3] * invtau + bv1.y + m1a;
            mx0 = fmaxf(mx0, fmaxf(s_acc[nt][0], s_acc[nt][1]));
            mx1 = fmaxf(mx1, fmaxf(s_acc[nt][2], s_acc[nt][3]));
        }
        mx0 = fmaxf(mx0, __shfl_xor_sync(0xffffffffu, mx0, 1));
        mx0 = fmaxf(mx0, __shfl_xor_sync(0xffffffffu, mx0, 2));
        mx1 = fmaxf(mx1, __shfl_xor_sync(0xffffffffu, mx1, 1));
        mx1 = fmaxf(mx1, __shfl_xor_sync(0xffffffffu, mx1, 2));

        float s0 = 0.f, s1 = 0.f;
#pragma unroll
        for (int nt = 0; nt < 8; nt++) {
            s_acc[nt][0] = __expf(s_acc[nt][0] - mx0);
            s_acc[nt][1] = __expf(s_acc[nt][1] - mx0);
            s_acc[nt][2] = __expf(s_acc[nt][2] - mx1);
            s_acc[nt][3] = __expf(s_acc[nt][3] - mx1);
            s0 += s_acc[nt][0] + s_acc[nt][1];
            s1 += s_acc[nt][2] + s_acc[nt][3];
        }
        s0 += __shfl_xor_sync(0xffffffffu, s0, 1);
        s0 += __shfl_xor_sync(0xffffffffu, s0, 2);
        s1 += __shfl_xor_sync(0xffffffffu, s1, 1);
        s1 += __shfl_xor_sync(0xffffffffu, s1, 2);
        float inv0 = 1.0f / s0, inv1 = 1.0f / s1;

#pragma unroll
        for (int nt = 0; nt < 8; nt++) {
            int j = nt * 8 + jb;
            float p00 = s_acc[nt][0] * inv0, p01 = s_acc[nt][1] * inv0;
            float p10 = s_acc[nt][2] * inv1, p11 = s_acc[nt][3] * inv1;
            *(float2*)(spf + r0 * 68 + j) = make_float2(p00, p01);
            *(float2*)(spf + r1 * 68 + j) = make_float2(p10, p11);
            *(__half2*)(sp + r0 * 72 + j) = __floats2half2_rn(p00, p01);
            *(__half2*)(sp + r1 * 72 + j) = __floats2half2_rn(p10, p11);
        }
        __syncthreads();

        // coalesced fp32 probs write
        float* ag = attn_out + (size_t)(g0 + wi) * 4096;
        for (int idx = t; idx < 1024; idx += 128) {
            int row = idx >> 4, c4 = (idx & 15) << 2;
            *(float4*)(ag + row * 64 + c4) = *(const float4*)(spf + row * 68 + c4);
        }

        // O = P @ V
        float o_acc[4][4];
#pragma unroll
        for (int nd = 0; nd < 4; nd++)
#pragma unroll
            for (int c = 0; c < 4; c++) o_acc[nd][c] = 0.f;

#pragma unroll
        for (int kt = 0; kt < 4; kt++) {
            unsigned af[4], bv[2][4];
            ldm4(af, spa + ((i0 + lr) * 72 + kt * 16 + lc) * 2);
#pragma unroll
            for (int ng = 0; ng < 2; ng++)
                ldm4t(bv[ng], buf + 10240 + ((kt * 16 + lr) * 40 + ng * 16 + lc) * 2);
#pragma unroll
            for (int nd = 0; nd < 4; nd++) {
                int ng = nd >> 1, q = nd & 1;
                mma16816(o_acc[nd], af, bv[ng][q * 2], bv[ng][q * 2 + 1]);
            }
        }
        __syncthreads();     // probs-write readers of spf done; reuse spf as O staging

        __half* sob = (__half*)spf;
#pragma unroll
        for (int nd = 0; nd < 4; nd++) {
            int d = nd * 8 + jb;
            *(__half2*)(sob + r0 * 40 + d) = __floats2half2_rn(o_acc[nd][0], o_acc[nd][1]);
            *(__half2*)(sob + r1 * 40 + d) = __floats2half2_rn(o_acc[nd][2], o_acc[nd][3]);
        }
        __syncthreads();

        const int Hb = (w >> 3) << 3, Wb = (w & 7) << 3;
        for (int f = t; f < 256; f += 128) {
            int tok = f >> 2, ch = (f & 3) * 8;
            int H = Hb + (tok >> 3), W = Wb + (tok & 7);
            size_t off = (size_t)((b << 12) + (H << 6) + W) * INNER + (h << 5) + ch;
            *(uint4*)(g_attnh + off) = *(const uint4*)(sob + tok * 40 + ch);
        }
    }
}

// ---------------------------------------------------------------------------
extern "C" void kernel_launch(void* const* d_in, const int* in_sizes, int n_in,
                              void* d_out, int out_size) {
    const float* x     = (const float*)d_in[0];
    const float* w_qkv = (const float*)d_in[1];
    const float* w1    = (const float*)d_in[2];
    const float* b1    = (const float*)d_in[3];
    const float* w2    = (const float*)d_in[4];
    const float* b2    = (const float*)d_in[5];
    const float* tau   = (const float*)d_in[6];
    const float* w_out = (const float*)d_in[7];
    const float* b_out = (const float*)d_in[8];

    float* out  = (float*)d_out;
    float* attn = out + (size_t)50331648;

    cudaFuncSetAttribute(gemm_qkv_tc, cudaFuncAttributeMaxDynamicSharedMemorySize, QKV_SMEM);
    cudaFuncSetAttribute(gemm_out_tc, cudaFuncAttributeMaxDynamicSharedMemorySize, OUT_SMEM);
    cudaFuncSetAttribute(attn_tc, cudaFuncAttributeMaxDynamicSharedMemorySize, ATTN_SMEM);

    cpb_kernel<<<16, 256>>>(w1, b1, w2, b2);
    cvt_weights<<<2304, 256>>>(w_qkv, w_out);
    shiftcvt_x<<<49152, 256>>>(x);
    gemm_qkv_tc<<<dim3(9, 1024), 256, QKV_SMEM>>>();
    attn_tc<<<3072, 128, ATTN_SMEM>>>(tau, attn);
    gemm_out_tc<<<dim3(3, 1024), 256, OUT_SMEM>>>(b_out, out);
}

// round 13
// speedup vs baseline: 1.0300x; 1.0300x over previous
#include <cuda_runtime.h>
#include <cuda_fp16.h>
#include <math.h>
#include <stdint.h>

#define BATCH   32
#define NHW     64
#define DIM     384
#define HEADS   12
#define HD      32
#define M2      64
#define NWIN    64
#define INNER   384
#define TOK     131072
#define QS      50331648ull

// Scratch
__device__ __half g_xh[(size_t)TOK * DIM];
__device__ __half g_wqh[1152 * 384];
__device__ __half g_woh[384 * 384];
__device__ __half g_qkvh[3ull * QS];
__device__ float  g_bias[HEADS * M2 * M2];
__device__ __half g_attnh[(size_t)TOK * INNER];

// ---------------------------------------------------------------------------
// helpers
// ---------------------------------------------------------------------------
__device__ __forceinline__ void ldm4(unsigned* r, unsigned addr) {
    asm volatile("ldmatrix.sync.aligned.m8n8.x4.shared.b16 {%0,%1,%2,%3}, [%4];"
                 : "=r"(r[0]), "=r"(r[1]), "=r"(r[2]), "=r"(r[3]) : "r"(addr));
}
__device__ __forceinline__ void ldm4t(unsigned* r, unsigned addr) {
    asm volatile("ldmatrix.sync.aligned.m8n8.x4.trans.shared.b16 {%0,%1,%2,%3}, [%4];"
                 : "=r"(r[0]), "=r"(r[1]), "=r"(r[2]), "=r"(r[3]) : "r"(addr));
}
__device__ __forceinline__ void mma16816(float* c, const unsigned* a, unsigned b0, unsigned b1) {
    asm volatile("mma.sync.aligned.m16n8k16.row.col.f32.f16.f16.f32 "
                 "{%0,%1,%2,%3}, {%4,%5,%6,%7}, {%8,%9}, {%0,%1,%2,%3};"
                 : "+f"(c[0]), "+f"(c[1]), "+f"(c[2]), "+f"(c[3])
                 : "r"(a[0]), "r"(a[1]), "r"(a[2]), "r"(a[3]), "r"(b0), "r"(b1));
}
__device__ __forceinline__ void cpa16(unsigned s, const void* g) {
    asm volatile("cp.async.cg.shared.global [%0], [%1], 16;" :: "r"(s), "l"(g));
}

// ---------------------------------------------------------------------------
// Merged preamble: shift+cvt x (blocks 0..49151), cvt weights (next 2304),
// CPB-MLP bias (last 16). All independent; one launch.
// ---------------------------------------------------------------------------
__global__ void __launch_bounds__(256) preamble_kernel(
        const float* __restrict__ X,
        const float* __restrict__ wq, const float* __restrict__ wo,
        const float* __restrict__ w1, const float* __restrict__ b1,
        const float* __restrict__ w2, const float* __restrict__ b2) {
    const int bid = blockIdx.x;
    const int t = threadIdx.x;

    if (bid < 49152) {
        // shift + convert x -> fp16
        int i4 = bid * 256 + t;
        int m = i4 / 96;
        int c = (i4 % 96) * 4;
        int b = m >> 12, H = (m >> 6) & 63, W = m & 63;
        int Hs = (H + 4) & 63, Ws = (W + 4) & 63;
        float4 v = *(const float4*)(X + (size_t)((b << 12) + (Hs << 6) + Ws) * DIM + c);
        __half2 h0 = __floats2half2_rn(v.x, v.y);
        __half2 h1 = __floats2half2_rn(v.z, v.w);
        uint2 out;
        out.x = *(unsigned*)&h0;
        out.y = *(unsigned*)&h1;
        *(uint2*)(g_xh + (size_t)m * DIM + c) = out;
        return;
    }
    if (bid < 49152 + 2304) {
        int i = (bid - 49152) * 256 + t;
        if (i < 442368) g_wqh[i] = __float2half_rn(wq[i]);
        else if (i < 442368 + 147456) g_woh[i - 442368] = __float2half_rn(wo[i - 442368]);
        return;
    }
    // CPB-MLP bias (16 blocks)
    __shared__ float w1s[1024];
    __shared__ float b1s[512];
    __shared__ float w2s[6144];
    for (int i = t; i < 1024; i += 256) w1s[i] = w1[i];
    for (int i = t; i < 512;  i += 256) b1s[i] = b1[i];
    for (int i = t; i < 6144; i += 256) w2s[i] = w2[i];
    __syncthreads();

    int idx = (bid - 49152 - 2304) * 256 + t;
    int i = idx >> 6, j = idx & 63;
    float dx = (float)((j >> 3) - (i >> 3));
    float dy = (float)((j & 7) - (i & 7));
    float cx = (dx >= 0.f) ? log1pf(dx) : -log1pf(-dx);
    float cy = (dy >= 0.f) ? log1pf(dy) : -log1pf(-dy);

    float acc[HEADS];
#pragma unroll
    for (int h = 0; h < HEADS; h++) acc[h] = b2[h];
    for (int h0 = 0; h0 < 512; h0++) {
        float hid = fmaxf(cx * w1s[2 * h0] + cy * w1s[2 * h0 + 1] + b1s[h0], 0.f);
#pragma unroll
        for (int h = 0; h < HEADS; h++) acc[h] += hid * w2s[h * 512 + h0];
    }
#pragma unroll
    for (int h = 0; h < HEADS; h++) g_bias[h * 4096 + idx] = acc[h];
}

// ---------------------------------------------------------------------------
// Shared GEMM pieces: 256 thr, CTA 128x128, kc=64, 2-stage (R3 mainloop)
// ---------------------------------------------------------------------------
#define GST 18432
#define QKV_SMEM (4 * GST)
#define OUT_SMEM (4 * GST)

__device__ __forceinline__ void gemm_issue64(unsigned sA, unsigned sB,
                                             const __half* gA, const __half* gB, int t) {
#pragma unroll
    for (int i = 0; i < 4; i++) {
        int idx = i * 256 + t;
        int row = idx >> 3, ch = (idx & 7) * 8;
        cpa16(sA + (row * 72 + ch) * 2, gA + (size_t)row * 384 + ch);
        cpa16(sB + (row * 72 + ch) * 2, gB + (size_t)row * 384 + ch);
    }
    asm volatile("cp.async.commit_group;");
}

__device__ __forceinline__ void gemm_stage64(float acc[4][4][4], unsigned sA, unsigned sB,
                                             int wm, int wn, int lr, int lc) {
#pragma unroll
    for (int ks = 0; ks < 4; ks++) {
        unsigned af[4][4], bf[2][4];
#pragma unroll
        for (int mt = 0; mt < 4; mt++)
            ldm4(af[mt], sA + ((wm * 64 + mt * 16 + lr) * 72 + ks * 16 + lc) * 2);
#pragma unroll
        for (int p = 0; p < 2; p++)
            ldm4(bf[p], sB + ((wn * 32 + p * 16 + lr) * 72 + ks * 16 + lc) * 2);
#pragma unroll
        for (int mt = 0; mt < 4; mt++)
#pragma unroll
            for (int nt = 0; nt < 4; nt++)
                mma16816(acc[mt][nt], af[mt], bf[nt >> 1][nt & 1], bf[nt >> 1][(nt & 1) + 2]);
    }
}

#define GEMM_MAINLOOP(GA, GB)                                                    \
    gemm_issue64(sb + 0 * GST, sb + 2 * GST + 0 * GST, (GA), (GB), t);           \
    for (int it = 0; it < 6; it++) {                                             \
        if (it + 1 < 6) {                                                        \
            int s2 = (it + 1) & 1;                                               \
            gemm_issue64(sb + s2 * GST, sb + 2 * GST + s2 * GST,                 \
                         (GA) + (it + 1) * 64, (GB) + (it + 1) * 64, t);         \
            asm volatile("cp.async.wait_group 1;");                              \
        } else {                                                                 \
            asm volatile("cp.async.wait_group 0;");                              \
        }                                                                        \
        __syncthreads();                                                         \
        int s = it & 1;                                                          \
        gemm_stage64(acc, sb + s * GST, sb + 2 * GST + s * GST, wm, wn, lr, lc); \
        __syncthreads();                                                         \
    }

// ---------------------------------------------------------------------------
// GEMM 1: qkv = g_xh @ g_wqh^T  (M=131072, N=1152, K=384)
// ---------------------------------------------------------------------------
__global__ void __launch_bounds__(256, 2) gemm_qkv_tc() {
    extern __shared__ __align__(16) char dsm[];
    __shared__ unsigned rowoff[128];
    const unsigned sb = (unsigned)__cvta_generic_to_shared(dsm);
    const int t = threadIdx.x;
    const int warp = t >> 5, lane = t & 31;
    const int wm = warp >> 2, wn = warp & 3;
    const int m0 = blockIdx.y * 128, n0 = blockIdx.x * 128;
    const int lr = lane & 15, lc = (lane >> 4) * 8;

    const __half* gA = g_xh + (size_t)m0 * 384;
    const __half* gB = g_wqh + (size_t)n0 * 384;

    float acc[4][4][4];
#pragma unroll
    for (int i = 0; i < 4; i++)
#pragma unroll
        for (int j = 0; j < 4; j++)
#pragma unroll
            for (int k = 0; k < 4; k++) acc[i][j][k] = 0.f;

    GEMM_MAINLOOP(gA, gB)

    __half* stg = (__half*)dsm;          // [128][136]
#pragma unroll
    for (int mt = 0; mt < 4; mt++)
#pragma unroll
        for (int nt = 0; nt < 4; nt++)
#pragma unroll
            for (int e = 0; e < 2; e++) {
                int r = wm * 64 + mt * 16 + (lane >> 2) + e * 8;
                int c = wn * 32 + nt * 8 + (lane & 3) * 2;
                *(__half2*)(stg + r * 136 + c) =
                    __floats2half2_rn(acc[mt][nt][e * 2], acc[mt][nt][e * 2 + 1]);
            }
    if (t < 128) {
        int m = m0 + t;
        int b = m >> 12, H = (m >> 6) & 63, W = m & 63;
        int win = ((H >> 3) << 3) + (W >> 3);
        int mm2 = ((H & 7) << 3) + (W & 7);
        rowoff[t] = (unsigned)(b * 1572864 + (win * 64 + mm2) * 32);
    }
    __syncthreads();

    const int qkvi = n0 / 384;
    const int hbase = (n0 % 384) >> 5;
    const __half* gq_base = g_qkvh + (size_t)qkvi * QS;
#pragma unroll
    for (int f = t; f < 2048; f += 256) {
        int ml = f >> 4, q = f & 15;
        int hc = q >> 2, i = q & 3;
        size_t off = (size_t)(hbase + hc) * 131072 + rowoff[ml] + i * 8;
        *(uint4*)((__half*)gq_base + off) = *(const uint4*)(stg + ml * 136 + hc * 32 + i * 8);
    }
}

// ---------------------------------------------------------------------------
// GEMM 2: out = g_attnh @ g_woh^T + b_out (M=131072, N=384, K=384)
// ---------------------------------------------------------------------------
__global__ void __launch_bounds__(256, 2) gemm_out_tc(const float* __restrict__ bo,
                                                      float* __restrict__ OUT) {
    extern __shared__ __align__(16) char dsm[];
    __shared__ unsigned rowoff[128];
    const unsigned sb = (unsigned)__cvta_generic_to_shared(dsm);
    const int t = threadIdx.x;
    const int warp = t >> 5, lane = t & 31;
    const int wm = warp >> 2, wn = warp & 3;
    const int m0 = blockIdx.y * 128, n0 = blockIdx.x * 128;
    const int lr = lane & 15, lc = (lane >> 4) * 8;

    const __half* gA = g_attnh + (size_t)m0 * 384;
    const __half* gB = g_woh + (size_t)n0 * 384;

    float acc[4][4][4];
#pragma unroll
    for (int i = 0; i < 4; i++)
#pragma unroll
        for (int j = 0; j < 4; j++)
#pragma unroll
            for (int k = 0; k < 4; k++) acc[i][j][k] = 0.f;

    GEMM_MAINLOOP(gA, gB)

    float* stg = (float*)dsm;            // [128][132]
#pragma unroll
    for (int mt = 0; mt < 4; mt++)
#pragma unroll
        for (int nt = 0; nt < 4; nt++) {
            int c = wn * 32 + nt * 8 + (lane & 3) * 2;
            float b0 = bo[n0 + c], b1 = bo[n0 + c + 1];
#pragma unroll
            for (int e = 0; e < 2; e++) {
                int r = wm * 64 + mt * 16 + (lane >> 2) + e * 8;
                *(float2*)(stg + r * 132 + c) =
                    make_float2(acc[mt][nt][e * 2] + b0, acc[mt][nt][e * 2 + 1] + b1);
            }
        }
    if (t < 128) {
        int m = m0 + t;
        int b = m >> 12, H = (m >> 6) & 63, W = m & 63;
        int Ho = (H + 4) & 63, Wo = (W + 4) & 63;
        rowoff[t] = (unsigned)(((b << 12) + (Ho << 6) + Wo) * 384);
    }
    __syncthreads();

#pragma unroll
    for (int f = t; f < 4096; f += 256) {
        int ml = f >> 5, c4 = (f & 31) * 4;
        *(float4*)(OUT + rowoff[ml] + n0 + c4) = *(const float4*)(stg + ml * 132 + c4);
    }
}

// ---------------------------------------------------------------------------
// Tensor-core attention: one CTA (128 thr) per (b,h,win).
// Normalize-on-load (register path), direct fp32 probs STG, 20.5KB smem.
// ---------------------------------------------------------------------------
__global__ void __launch_bounds__(128) attn_tc(const float* __restrict__ tau,
                                               float* __restrict__ attn_out) {
    __shared__ __align__(16) __half qkp[5120];    // sq[64*40]|sk[64*40] ; later sp[64*72]
    __shared__ __align__(16) __half sv[64 * 40];
    __shared__ __align__(16) __half sob[64 * 40]; // O staging

    __half* sq = qkp;
    __half* sk = qkp + 2560;
    __half* sp = qkp;                             // alias, valid after QK mma

    const int bid = blockIdx.x;
    const int w = bid & 63;
    const int h = (bid >> 6) % HEADS;
    const int b = bid / (HEADS * NWIN);
    const int t = threadIdx.x;
    const int lane = t & 31, warp = t >> 5;

    const size_t base = ((size_t)(b * HEADS + h) * NWIN + w) * 2048;
    const __half* gq = g_qkvh + base;
    const __half* gk = g_qkvh + QS + base;
    const __half* gv = g_qkvh + 2ull * QS + base;

    // q/k: one row per thread, L2-normalize in registers, single smem write
    {
        const __half* src = (t < 64) ? (gq + (size_t)(t & 63) * 32)
                                     : (gk + (size_t)(t & 63) * 32);
        __half* dst = ((t < 64) ? sq : sk) + (t & 63) * 40;
        uint4 rwd[4];
#pragma unroll
        for (int i = 0; i < 4; i++) rwd[i] = *(const uint4*)(src + i * 8);
        __half2* hp = (__half2*)rwd;
        float2 fv[16];
        float ss = 0.f;
#pragma unroll
        for (int i = 0; i < 16; i++) {
            fv[i] = __half22float2(hp[i]);
            ss += fv[i].x * fv[i].x + fv[i].y * fv[i].y;
        }
        float sc = 1.f / fmaxf(sqrtf(ss), 1e-12f);
#pragma unroll
        for (int i = 0; i < 16; i++)
            hp[i] = __floats2half2_rn(fv[i].x * sc, fv[i].y * sc);
#pragma unroll
        for (int i = 0; i < 4; i++) *(uint4*)(dst + i * 8) = rwd[i];
    }
    // v: coalesced strided load
    for (int f = t; f < 256; f += 128) {
        int row = f >> 2, ch = (f & 3) * 8;
        *(uint4*)(sv + row * 40 + ch) = *(const uint4*)(gv + row * 32 + ch);
    }
    __syncthreads();

    const unsigned sqa = (unsigned)__cvta_generic_to_shared(sq);
    const unsigned ska = (unsigned)__cvta_generic_to_shared(sk);
    const unsigned sva = (unsigned)__cvta_generic_to_shared(sv);
    const unsigned spa = (unsigned)__cvta_generic_to_shared(sp);
    const int lr = lane & 15, lc = (lane >> 4) * 8;
    const int i0 = warp * 16;

    // S = q @ k^T
    float s_acc[8][4];
#pragma unroll
    for (int nt = 0; nt < 8; nt++)
#pragma unroll
        for (int c = 0; c < 4; c++) s_acc[nt][c] = 0.f;

#pragma unroll
    for (int ks = 0; ks < 2; ks++) {
        unsigned af[4], bf[4][4];
        ldm4(af, sqa + ((i0 + lr) * 40 + ks * 16 + lc) * 2);
#pragma unroll
        for (int p = 0; p < 4; p++)
            ldm4(bf[p], ska + ((p * 16 + lr) * 40 + ks * 16 + lc) * 2);
#pragma unroll
        for (int nt = 0; nt < 8; nt++)
            mma16816(s_acc[nt], af, bf[nt >> 1][nt & 1], bf[nt >> 1][(nt & 1) + 2]);
    }
    __syncthreads();    // sq/sk dead -> reuse as sp

    const float invtau = 1.0f / fmaxf(tau[h], 0.01f);
    const bool ulm = (w >= 56);
    const bool lrm = ((w & 7) == 7);
    const float* bb = g_bias + h * 4096;
    const int r0 = i0 + (lane >> 2);
    const int r1 = r0 + 8;
    const int jb = (lane & 3) * 2;
    const bool i0ge = (r0 >= 32), i1ge = (r1 >= 32);
    const bool ih = ((r0 & 7) >= 4);

    float mx0 = -1e38f, mx1 = -1e38f;
#pragma unroll
    for (int nt = 0; nt < 8; nt++) {
        int j = nt * 8 + jb;
        bool jge = (j >= 32), jh = ((j & 7) >= 4);
        float2 bv0 = *(const float2*)(bb + r0 * 64 + j);
        float2 bv1 = *(const float2*)(bb + r1 * 64 + j);
        float m0a = ((ulm && (i0ge != jge)) || (lrm && (ih != jh))) ? -1e30f : 0.f;
        float m1a = ((ulm && (i1ge != jge)) || (lrm && (ih != jh))) ? -1e30f : 0.f;
        s_acc[nt][0] = s_acc[nt][0] * invtau + bv0.x + m0a;
        s_acc[nt][1] = s_acc[nt][1] * invtau + bv0.y + m0a;
        s_acc[nt][2] = s_acc[nt][2] * invtau + bv1.x + m1a;
        s_acc[nt][3] = s_acc[nt][3] * invtau + bv1.y + m1a;
        mx0 = fmaxf(mx0, fmaxf(s_acc[nt][0], s_acc[nt][1]));
        mx1 = fmaxf(mx1, fmaxf(s_acc[nt][2], s_acc[nt][3]));
    }
    mx0 = fmaxf(mx0, __shfl_xor_sync(0xffffffffu, mx0, 1));
    mx0 = fmaxf(mx0, __shfl_xor_sync(0xffffffffu, mx0, 2));
    mx1 = fmaxf(mx1, __shfl_xor_sync(0xffffffffu, mx1, 1));
    mx1 = fmaxf(mx1, __shfl_xor_sync(0xffffffffu, mx1, 2));

    float s0 = 0.f, s1 = 0.f;
#pragma unroll
    for (int nt = 0; nt < 8; nt++) {
        s_acc[nt][0] = __expf(s_acc[nt][0] - mx0);
        s_acc[nt][1] = __expf(s_acc[nt][1] - mx0);
        s_acc[nt][2] = __expf(s_acc[nt][2] - mx1);
        s_acc[nt][3] = __expf(s_acc[nt][3] - mx1);
        s0 += s_acc[nt][0] + s_acc[nt][1];
        s1 += s_acc[nt][2] + s_acc[nt][3];
    }
    s0 += __shfl_xor_sync(0xffffffffu, s0, 1);
    s0 += __shfl_xor_sync(0xffffffffu, s0, 2);
    s1 += __shfl_xor_sync(0xffffffffu, s1, 1);
    s1 += __shfl_xor_sync(0xffffffffu, s1, 2);
    float inv0 = 1.0f / s0, inv1 = 1.0f / s1;

    // probs: fp16 to smem (for PV), fp32 direct to gmem (32B-sector coalesced)
    float* ag = attn_out + (size_t)bid * 4096;
#pragma unroll
    for (int nt = 0; nt < 8; nt++) {
        int j = nt * 8 + jb;
        float p00 = s_acc[nt][0] * inv0, p01 = s_acc[nt][1] * inv0;
        float p10 = s_acc[nt][2] * inv1, p11 = s_acc[nt][3] * inv1;
        *(__half2*)(sp + r0 * 72 + j) = __floats2half2_rn(p00, p01);
        *(__half2*)(sp + r1 * 72 + j) = __floats2half2_rn(p10, p11);
        *(float2*)(ag + r0 * 64 + j) = make_float2(p00, p01);
        *(float2*)(ag + r1 * 64 + j) = make_float2(p10, p11);
    }
    __syncthreads();

    // O = P @ V
    float o_acc[4][4];
#pragma unroll
    for (int nd = 0; nd < 4; nd++)
#pragma unroll
        for (int c = 0; c < 4; c++) o_acc[nd][c] = 0.f;

#pragma unroll
    for (int kt = 0; kt < 4; kt++) {
        unsigned af[4], bv[2][4];
        ldm4(af, spa + ((i0 + lr) * 72 + kt * 16 + lc) * 2);
#pragma unroll
        for (int ng = 0; ng < 2; ng++)
            ldm4t(bv[ng], sva + ((kt * 16 + lr) * 40 + ng * 16 + lc) * 2);
#pragma unroll
        for (int nd = 0; nd < 4; nd++) {
            int ng = nd >> 1, q = nd & 1;
            mma16816(o_acc[nd], af, bv[ng][q * 2], bv[ng][q * 2 + 1]);
        }
    }

    // stage O in its own buffer (no alias with sp -> no barrier needed before)
#pragma unroll
    for (int nd = 0; nd < 4; nd++) {
        int d = nd * 8 + jb;
        *(__half2*)(sob + r0 * 40 + d) = __floats2half2_rn(o_acc[nd][0], o_acc[nd][1]);
        *(__half2*)(sob + r1 * 40 + d) = __floats2half2_rn(o_acc[nd][2], o_acc[nd][3]);
    }
    __syncthreads();

    const int Hb = (w >> 3) << 3, Wb = (w & 7) << 3;
    for (int f = t; f < 256; f += 128) {
        int tok = f >> 2, ch = (f & 3) * 8;
        int H = Hb + (tok >> 3), W = Wb + (tok & 7);
        size_t off = (size_t)((b << 12) + (H << 6) + W) * INNER + (h << 5) + ch;
        *(uint4*)(g_attnh + off) = *(const uint4*)(sob + tok * 40 + ch);
    }
}

// ---------------------------------------------------------------------------
extern "C" void kernel_launch(void* const* d_in, const int* in_sizes, int n_in,
                              void* d_out, int out_size) {
    const float* x     = (const float*)d_in[0];
    const float* w_qkv = (const float*)d_in[1];
    const float* w1    = (const float*)d_in[2];
    const float* b1    = (const float*)d_in[3];
    const float* w2    = (const float*)d_in[4];
    const float* b2    = (const float*)d_in[5];
    const float* tau   = (const float*)d_in[6];
    const float* w_out = (const float*)d_in[7];
    const float* b_out = (const float*)d_in[8];

    float* out  = (float*)d_out;
    float* attn = out + (size_t)50331648;

    cudaFuncSetAttribute(gemm_qkv_tc, cudaFuncAttributeMaxDynamicSharedMemorySize, QKV_SMEM);
    cudaFuncSetAttribute(gemm_out_tc, cudaFuncAttributeMaxDynamicSharedMemorySize, OUT_SMEM);

    preamble_kernel<<<49152 + 2304 + 16, 256>>>(x, w_qkv, w_out, w1, b1, w2, b2);
    gemm_qkv_tc<<<dim3(9, 1024), 256, QKV_SMEM>>>();
    attn_tc<<<24576, 128>>>(tau, attn);
    gemm_out_tc<<<dim3(3, 1024), 256, OUT_SMEM>>>(b_out, out);
}

// round 14
// speedup vs baseline: 1.0421x; 1.0117x over previous
#include <cuda_runtime.h>
#include <cuda_fp16.h>
#include <math.h>
#include <stdint.h>

#define BATCH   32
#define NHW     64
#define DIM     384
#define HEADS   12
#define HD      32
#define M2      64
#define NWIN    64
#define INNER   384
#define TOK     131072
#define QS      50331648ull

// Scratch
__device__ __half g_xh[(size_t)TOK * DIM];
__device__ __half g_wqh[1152 * 384];
__device__ __half g_woh[384 * 384];
__device__ __half g_qkvh[3ull * QS];
__device__ float  g_bias[HEADS * M2 * M2];
__device__ __half g_attnh[(size_t)TOK * INNER];

// ---------------------------------------------------------------------------
// helpers
// ---------------------------------------------------------------------------
__device__ __forceinline__ void ldm4(unsigned* r, unsigned addr) {
    asm volatile("ldmatrix.sync.aligned.m8n8.x4.shared.b16 {%0,%1,%2,%3}, [%4];"
                 : "=r"(r[0]), "=r"(r[1]), "=r"(r[2]), "=r"(r[3]) : "r"(addr));
}
__device__ __forceinline__ void ldm4t(unsigned* r, unsigned addr) {
    asm volatile("ldmatrix.sync.aligned.m8n8.x4.trans.shared.b16 {%0,%1,%2,%3}, [%4];"
                 : "=r"(r[0]), "=r"(r[1]), "=r"(r[2]), "=r"(r[3]) : "r"(addr));
}
__device__ __forceinline__ void mma16816(float* c, const unsigned* a, unsigned b0, unsigned b1) {
    asm volatile("mma.sync.aligned.m16n8k16.row.col.f32.f16.f16.f32 "
                 "{%0,%1,%2,%3}, {%4,%5,%6,%7}, {%8,%9}, {%0,%1,%2,%3};"
                 : "+f"(c[0]), "+f"(c[1]), "+f"(c[2]), "+f"(c[3])
                 : "r"(a[0]), "r"(a[1]), "r"(a[2]), "r"(a[3]), "r"(b0), "r"(b1));
}
__device__ __forceinline__ void cpa16(unsigned s, const void* g) {
    asm volatile("cp.async.cg.shared.global [%0], [%1], 16;" :: "r"(s), "l"(g));
}

// ---------------------------------------------------------------------------
// Merged preamble: shift+cvt x | cvt weights | CPB bias (one launch)
// ---------------------------------------------------------------------------
__global__ void __launch_bounds__(256) preamble_kernel(
        const float* __restrict__ X,
        const float* __restrict__ wq, const float* __restrict__ wo,
        const float* __restrict__ w1, const float* __restrict__ b1,
        const float* __restrict__ w2, const float* __restrict__ b2) {
    const int bid = blockIdx.x;
    const int t = threadIdx.x;

    if (bid < 49152) {
        int i4 = bid * 256 + t;
        int m = i4 / 96;
        int c = (i4 % 96) * 4;
        int b = m >> 12, H = (m >> 6) & 63, W = m & 63;
        int Hs = (H + 4) & 63, Ws = (W + 4) & 63;
        float4 v = *(const float4*)(X + (size_t)((b << 12) + (Hs << 6) + Ws) * DIM + c);
        __half2 h0 = __floats2half2_rn(v.x, v.y);
        __half2 h1 = __floats2half2_rn(v.z, v.w);
        uint2 out;
        out.x = *(unsigned*)&h0;
        out.y = *(unsigned*)&h1;
        *(uint2*)(g_xh + (size_t)m * DIM + c) = out;
        return;
    }
    if (bid < 49152 + 2304) {
        int i = (bid - 49152) * 256 + t;
        if (i < 442368) g_wqh[i] = __float2half_rn(wq[i]);
        else if (i < 442368 + 147456) g_woh[i - 442368] = __float2half_rn(wo[i - 442368]);
        return;
    }
    __shared__ float w1s[1024];
    __shared__ float b1s[512];
    __shared__ float w2s[6144];
    for (int i = t; i < 1024; i += 256) w1s[i] = w1[i];
    for (int i = t; i < 512;  i += 256) b1s[i] = b1[i];
    for (int i = t; i < 6144; i += 256) w2s[i] = w2[i];
    __syncthreads();

    int idx = (bid - 49152 - 2304) * 256 + t;
    int i = idx >> 6, j = idx & 63;
    float dx = (float)((j >> 3) - (i >> 3));
    float dy = (float)((j & 7) - (i & 7));
    float cx = (dx >= 0.f) ? log1pf(dx) : -log1pf(-dx);
    float cy = (dy >= 0.f) ? log1pf(dy) : -log1pf(-dy);

    float acc[HEADS];
#pragma unroll
    for (int h = 0; h < HEADS; h++) acc[h] = b2[h];
    for (int h0 = 0; h0 < 512; h0++) {
        float hid = fmaxf(cx * w1s[2 * h0] + cy * w1s[2 * h0 + 1] + b1s[h0], 0.f);
#pragma unroll
        for (int h = 0; h < HEADS; h++) acc[h] += hid * w2s[h * 512 + h0];
    }
#pragma unroll
    for (int h = 0; h < HEADS; h++) g_bias[h * 4096 + idx] = acc[h];
}

// ---------------------------------------------------------------------------
// Shared GEMM pieces: 256 thr, CTA 128x128, kc=64, 2-stage (R3 mainloop)
// ---------------------------------------------------------------------------
#define GST 18432
#define QKV_SMEM (4 * GST)
#define OUT_SMEM (4 * GST)

__device__ __forceinline__ void gemm_issue64(unsigned sA, unsigned sB,
                                             const __half* gA, const __half* gB, int t) {
#pragma unroll
    for (int i = 0; i < 4; i++) {
        int idx = i * 256 + t;
        int row = idx >> 3, ch = (idx & 7) * 8;
        cpa16(sA + (row * 72 + ch) * 2, gA + (size_t)row * 384 + ch);
        cpa16(sB + (row * 72 + ch) * 2, gB + (size_t)row * 384 + ch);
    }
    asm volatile("cp.async.commit_group;");
}

__device__ __forceinline__ void gemm_stage64(float acc[4][4][4], unsigned sA, unsigned sB,
                                             int wm, int wn, int lr, int lc) {
#pragma unroll
    for (int ks = 0; ks < 4; ks++) {
        unsigned af[4][4], bf[2][4];
#pragma unroll
        for (int mt = 0; mt < 4; mt++)
            ldm4(af[mt], sA + ((wm * 64 + mt * 16 + lr) * 72 + ks * 16 + lc) * 2);
#pragma unroll
        for (int p = 0; p < 2; p++)
            ldm4(bf[p], sB + ((wn * 32 + p * 16 + lr) * 72 + ks * 16 + lc) * 2);
#pragma unroll
        for (int mt = 0; mt < 4; mt++)
#pragma unroll
            for (int nt = 0; nt < 4; nt++)
                mma16816(acc[mt][nt], af[mt], bf[nt >> 1][nt & 1], bf[nt >> 1][(nt & 1) + 2]);
    }
}

#define GEMM_MAINLOOP(GA, GB)                                                    \
    gemm_issue64(sb + 0 * GST, sb + 2 * GST + 0 * GST, (GA), (GB), t);           \
    for (int it = 0; it < 6; it++) {                                             \
        if (it + 1 < 6) {                                                        \
            int s2 = (it + 1) & 1;                                               \
            gemm_issue64(sb + s2 * GST, sb + 2 * GST + s2 * GST,                 \
                         (GA) + (it + 1) * 64, (GB) + (it + 1) * 64, t);         \
            asm volatile("cp.async.wait_group 1;");                              \
        } else {                                                                 \
            asm volatile("cp.async.wait_group 0;");                              \
        }                                                                        \
        __syncthreads();                                                         \
        int s = it & 1;                                                          \
        gemm_stage64(acc, sb + s * GST, sb + 2 * GST + s * GST, wm, wn, lr, lc); \
        __syncthreads();                                                         \
    }

// ---------------------------------------------------------------------------
// GEMM 1: qkv = g_xh @ g_wqh^T  (M=131072, N=1152, K=384)
// ---------------------------------------------------------------------------
__global__ void __launch_bounds__(256, 2) gemm_qkv_tc() {
    extern __shared__ __align__(16) char dsm[];
    __shared__ unsigned rowoff[128];
    const unsigned sb = (unsigned)__cvta_generic_to_shared(dsm);
    const int t = threadIdx.x;
    const int warp = t >> 5, lane = t & 31;
    const int wm = warp >> 2, wn = warp & 3;
    const int m0 = blockIdx.y * 128, n0 = blockIdx.x * 128;
    const int lr = lane & 15, lc = (lane >> 4) * 8;

    const __half* gA = g_xh + (size_t)m0 * 384;
    const __half* gB = g_wqh + (size_t)n0 * 384;

    float acc[4][4][4];
#pragma unroll
    for (int i = 0; i < 4; i++)
#pragma unroll
        for (int j = 0; j < 4; j++)
#pragma unroll
            for (int k = 0; k < 4; k++) acc[i][j][k] = 0.f;

    GEMM_MAINLOOP(gA, gB)

    __half* stg = (__half*)dsm;          // [128][136]
#pragma unroll
    for (int mt = 0; mt < 4; mt++)
#pragma unroll
        for (int nt = 0; nt < 4; nt++)
#pragma unroll
            for (int e = 0; e < 2; e++) {
                int r = wm * 64 + mt * 16 + (lane >> 2) + e * 8;
                int c = wn * 32 + nt * 8 + (lane & 3) * 2;
                *(__half2*)(stg + r * 136 + c) =
                    __floats2half2_rn(acc[mt][nt][e * 2], acc[mt][nt][e * 2 + 1]);
            }
    if (t < 128) {
        int m = m0 + t;
        int b = m >> 12, H = (m >> 6) & 63, W = m & 63;
        int win = ((H >> 3) << 3) + (W >> 3);
        int mm2 = ((H & 7) << 3) + (W & 7);
        rowoff[t] = (unsigned)(b * 1572864 + (win * 64 + mm2) * 32);
    }
    __syncthreads();

    const int qkvi = n0 / 384;
    const int hbase = (n0 % 384) >> 5;
    const __half* gq_base = g_qkvh + (size_t)qkvi * QS;
#pragma unroll
    for (int f = t; f < 2048; f += 256) {
        int ml = f >> 4, q = f & 15;
        int hc = q >> 2, i = q & 3;
        size_t off = (size_t)(hbase + hc) * 131072 + rowoff[ml] + i * 8;
        *(uint4*)((__half*)gq_base + off) = *(const uint4*)(stg + ml * 136 + hc * 32 + i * 8);
    }
}

// ---------------------------------------------------------------------------
// GEMM 2: out = g_attnh @ g_woh^T + b_out (M=131072, N=384, K=384)
// ---------------------------------------------------------------------------
__global__ void __launch_bounds__(256, 2) gemm_out_tc(const float* __restrict__ bo,
                                                      float* __restrict__ OUT) {
    extern __shared__ __align__(16) char dsm[];
    __shared__ unsigned rowoff[128];
    const unsigned sb = (unsigned)__cvta_generic_to_shared(dsm);
    const int t = threadIdx.x;
    const int warp = t >> 5, lane = t & 31;
    const int wm = warp >> 2, wn = warp & 3;
    const int m0 = blockIdx.y * 128, n0 = blockIdx.x * 128;
    const int lr = lane & 15, lc = (lane >> 4) * 8;

    const __half* gA = g_attnh + (size_t)m0 * 384;
    const __half* gB = g_woh + (size_t)n0 * 384;

    float acc[4][4][4];
#pragma unroll
    for (int i = 0; i < 4; i++)
#pragma unroll
        for (int j = 0; j < 4; j++)
#pragma unroll
            for (int k = 0; k < 4; k++) acc[i][j][k] = 0.f;

    GEMM_MAINLOOP(gA, gB)

    float* stg = (float*)dsm;            // [128][132]
#pragma unroll
    for (int mt = 0; mt < 4; mt++)
#pragma unroll
        for (int nt = 0; nt < 4; nt++) {
            int c = wn * 32 + nt * 8 + (lane & 3) * 2;
            float b0 = bo[n0 + c], b1 = bo[n0 + c + 1];
#pragma unroll
            for (int e = 0; e < 2; e++) {
                int r = wm * 64 + mt * 16 + (lane >> 2) + e * 8;
                *(float2*)(stg + r * 132 + c) =
                    make_float2(acc[mt][nt][e * 2] + b0, acc[mt][nt][e * 2 + 1] + b1);
            }
        }
    if (t < 128) {
        int m = m0 + t;
        int b = m >> 12, H = (m >> 6) & 63, W = m & 63;
        int Ho = (H + 4) & 63, Wo = (W + 4) & 63;
        rowoff[t] = (unsigned)(((b << 12) + (Ho << 6) + Wo) * 384);
    }
    __syncthreads();

#pragma unroll
    for (int f = t; f < 4096; f += 256) {
        int ml = f >> 5, c4 = (f & 31) * 4;
        *(float4*)(OUT + rowoff[ml] + n0 + c4) = *(const float4*)(stg + ml * 132 + c4);
    }
}

// ---------------------------------------------------------------------------
// Tensor-core attention: one CTA (128 thr) per (b,h,win).
// Register-resident P: S-fragments feed PV directly (no P smem round-trip).
// Only 2 barriers. smem ~20KB.
// ---------------------------------------------------------------------------
__global__ void __launch_bounds__(128) attn_tc(const float* __restrict__ tau,
                                               float* __restrict__ attn_out) {
    __shared__ __align__(16) __half sq[64 * 40];
    __shared__ __align__(16) __half sk[64 * 40];
    __shared__ __align__(16) __half sv[64 * 40];
    __shared__ __align__(16) __half sob[64 * 40]; // O staging

    const int bid = blockIdx.x;
    const int w = bid & 63;
    const int h = (bid >> 6) % HEADS;
    const int b = bid / (HEADS * NWIN);
    const int t = threadIdx.x;
    const int lane = t & 31, warp = t >> 5;

    const size_t base = ((size_t)(b * HEADS + h) * NWIN + w) * 2048;
    const __half* gq = g_qkvh + base;
    const __half* gk = g_qkvh + QS + base;
    const __half* gv = g_qkvh + 2ull * QS + base;

    // q/k: one row per thread, L2-normalize in registers, single smem write
    {
        const __half* src = (t < 64) ? (gq + (size_t)(t & 63) * 32)
                                     : (gk + (size_t)(t & 63) * 32);
        __half* dst = ((t < 64) ? sq : sk) + (t & 63) * 40;
        uint4 rwd[4];
#pragma unroll
        for (int i = 0; i < 4; i++) rwd[i] = *(const uint4*)(src + i * 8);
        __half2* hp = (__half2*)rwd;
        float2 fv[16];
        float ss = 0.f;
#pragma unroll
        for (int i = 0; i < 16; i++) {
            fv[i] = __half22float2(hp[i]);
            ss += fv[i].x * fv[i].x + fv[i].y * fv[i].y;
        }
        float sc = 1.f / fmaxf(sqrtf(ss), 1e-12f);
#pragma unroll
        for (int i = 0; i < 16; i++)
            hp[i] = __floats2half2_rn(fv[i].x * sc, fv[i].y * sc);
#pragma unroll
        for (int i = 0; i < 4; i++) *(uint4*)(dst + i * 8) = rwd[i];
    }
    // v: coalesced strided load
    for (int f = t; f < 256; f += 128) {
        int row = f >> 2, ch = (f & 3) * 8;
        *(uint4*)(sv + row * 40 + ch) = *(const uint4*)(gv + row * 32 + ch);
    }
    __syncthreads();

    const unsigned sqa = (unsigned)__cvta_generic_to_shared(sq);
    const unsigned ska = (unsigned)__cvta_generic_to_shared(sk);
    const unsigned sva = (unsigned)__cvta_generic_to_shared(sv);
    const int lr = lane & 15, lc = (lane >> 4) * 8;
    const int i0 = warp * 16;

    // S = q @ k^T
    float s_acc[8][4];
#pragma unroll
    for (int nt = 0; nt < 8; nt++)
#pragma unroll
        for (int c = 0; c < 4; c++) s_acc[nt][c] = 0.f;

#pragma unroll
    for (int ks = 0; ks < 2; ks++) {
        unsigned af[4], bf[4][4];
        ldm4(af, sqa + ((i0 + lr) * 40 + ks * 16 + lc) * 2);
#pragma unroll
        for (int p = 0; p < 4; p++)
            ldm4(bf[p], ska + ((p * 16 + lr) * 40 + ks * 16 + lc) * 2);
#pragma unroll
        for (int nt = 0; nt < 8; nt++)
            mma16816(s_acc[nt], af, bf[nt >> 1][nt & 1], bf[nt >> 1][(nt & 1) + 2]);
    }

    const float invtau = 1.0f / fmaxf(tau[h], 0.01f);
    const bool ulm = (w >= 56);
    const bool lrm = ((w & 7) == 7);
    const float* bb = g_bias + h * 4096;
    const int r0 = i0 + (lane >> 2);
    const int r1 = r0 + 8;
    const int jb = (lane & 3) * 2;
    const bool i0ge = (r0 >= 32), i1ge = (r1 >= 32);
    const bool ih = ((r0 & 7) >= 4);

    float mx0 = -1e38f, mx1 = -1e38f;
#pragma unroll
    for (int nt = 0; nt < 8; nt++) {
        int j = nt * 8 + jb;
        bool jge = (j >= 32), jh = ((j & 7) >= 4);
        float2 bv0 = *(const float2*)(bb + r0 * 64 + j);
        float2 bv1 = *(const float2*)(bb + r1 * 64 + j);
        float m0a = ((ulm && (i0ge != jge)) || (lrm && (ih != jh))) ? -1e30f : 0.f;
        float m1a = ((ulm && (i1ge != jge)) || (lrm && (ih != jh))) ? -1e30f : 0.f;
        s_acc[nt][0] = s_acc[nt][0] * invtau + bv0.x + m0a;
        s_acc[nt][1] = s_acc[nt][1] * invtau + bv0.y + m0a;
        s_acc[nt][2] = s_acc[nt][2] * invtau + bv1.x + m1a;
        s_acc[nt][3] = s_acc[nt][3] * invtau + bv1.y + m1a;
        mx0 = fmaxf(mx0, fmaxf(s_acc[nt][0], s_acc[nt][1]));
        mx1 = fmaxf(mx1, fmaxf(s_acc[nt][2], s_acc[nt][3]));
    }
    mx0 = fmaxf(mx0, __shfl_xor_sync(0xffffffffu, mx0, 1));
    mx0 = fmaxf(mx0, __shfl_xor_sync(0xffffffffu, mx0, 2));
    mx1 = fmaxf(mx1, __shfl_xor_sync(0xffffffffu, mx1, 1));
    mx1 = fmaxf(mx1, __shfl_xor_sync(0xffffffffu, mx1, 2));

    float s0 = 0.f, s1 = 0.f;
#pragma unroll
    for (int nt = 0; nt < 8; nt++) {
        s_acc[nt][0] = __expf(s_acc[nt][0] - mx0);
        s_acc[nt][1] = __expf(s_acc[nt][1] - mx0);
        s_acc[nt][2] = __expf(s_acc[nt][2] - mx1);
        s_acc[nt][3] = __expf(s_acc[nt][3] - mx1);
        s0 += s_acc[nt][0] + s_acc[nt][1];
        s1 += s_acc[nt][2] + s_acc[nt][3];
    }
    s0 += __shfl_xor_sync(0xffffffffu, s0, 1);
    s0 += __shfl_xor_sync(0xffffffffu, s0, 2);
    s1 += __shfl_xor_sync(0xffffffffu, s1, 1);
    s1 += __shfl_xor_sync(0xffffffffu, s1, 2);
    float inv0 = 1.0f / s0, inv1 = 1.0f / s1;

    // probs: fp32 direct to gmem + fp16 A-fragments in registers
    float* ag = attn_out + (size_t)bid * 4096;
    unsigned pfrag[4][4];     // [kt][a0..a3] for PV
#pragma unroll
    for (int nt = 0; nt < 8; nt++) {
        int j = nt * 8 + jb;
        float p00 = s_acc[nt][0] * inv0, p01 = s_acc[nt][1] * inv0;
        float p10 = s_acc[nt][2] * inv1, p11 = s_acc[nt][3] * inv1;
        *(float2*)(ag + r0 * 64 + j) = make_float2(p00, p01);
        *(float2*)(ag + r1 * 64 + j) = make_float2(p10, p11);
        __half2 h0 = __floats2half2_rn(p00, p01);
        __half2 h1 = __floats2half2_rn(p10, p11);
        // nt = 2*kt + half : a-index = (nt&1)*2 + {0 for rows r0, 1 for rows r1}
        pfrag[nt >> 1][(nt & 1) * 2 + 0] = *(unsigned*)&h0;
        pfrag[nt >> 1][(nt & 1) * 2 + 1] = *(unsigned*)&h1;
    }

    // O = P @ V  (P from registers; V via ldmatrix.trans)
    float o_acc[4][4];
#pragma unroll
    for (int nd = 0; nd < 4; nd++)
#pragma unroll
        for (int c = 0; c < 4; c++) o_acc[nd][c] = 0.f;

#pragma unroll
    for (int kt = 0; kt < 4; kt++) {
        unsigned bv[2][4];
#pragma unroll
        for (int ng = 0; ng < 2; ng++)
            ldm4t(bv[ng], sva + ((kt * 16 + lr) * 40 + ng * 16 + lc) * 2);
#pragma unroll
        for (int nd = 0; nd < 4; nd++) {
            int ng = nd >> 1, q = nd & 1;
            mma16816(o_acc[nd], pfrag[kt], bv[ng][q * 2], bv[ng][q * 2 + 1]);
        }
    }

    // stage O (own buffer; no alias) then coalesced write
#pragma unroll
    for (int nd = 0; nd < 4; nd++) {
        int d = nd * 8 + jb;
        *(__half2*)(sob + r0 * 40 + d) = __floats2half2_rn(o_acc[nd][0], o_acc[nd][1]);
        *(__half2*)(sob + r1 * 40 + d) = __floats2half2_rn(o_acc[nd][2], o_acc[nd][3]);
    }
    __syncthreads();

    const int Hb = (w >> 3) << 3, Wb = (w & 7) << 3;
    for (int f = t; f < 256; f += 128) {
        int tok = f >> 2, ch = (f & 3) * 8;
        int H = Hb + (tok >> 3), W = Wb + (tok & 7);
        size_t off = (size_t)((b << 12) + (H << 6) + W) * INNER + (h << 5) + ch;
        *(uint4*)(g_attnh + off) = *(const uint4*)(sob + tok * 40 + ch);
    }
}

// ---------------------------------------------------------------------------
extern "C" void kernel_launch(void* const* d_in, const int* in_sizes, int n_in,
                              void* d_out, int out_size) {
    const float* x     = (const float*)d_in[0];
    const float* w_qkv = (const float*)d_in[1];
    const float* w1    = (const float*)d_in[2];
    const float* b1    = (const float*)d_in[3];
    const float* w2    = (const float*)d_in[4];
    const float* b2    = (const float*)d_in[5];
    const float* tau   = (const float*)d_in[6];
    const float* w_out = (const float*)d_in[7];
    const float* b_out = (const float*)d_in[8];

    float* out  = (float*)d_out;
    float* attn = out + (size_t)50331648;

    cudaFuncSetAttribute(gemm_qkv_tc, cudaFuncAttributeMaxDynamicSharedMemorySize, QKV_SMEM);
    cudaFuncSetAttribute(gemm_out_tc, cudaFuncAttributeMaxDynamicSharedMemorySize, OUT_SMEM);

    preamble_kernel<<<49152 + 2304 + 16, 256>>>(x, w_qkv, w_out, w1, b1, w2, b2);
    gemm_qkv_tc<<<dim3(9, 1024), 256, QKV_SMEM>>>();
    attn_tc<<<24576, 128>>>(tau, attn);
    gemm_out_tc<<<dim3(3, 1024), 256, OUT_SMEM>>>(b_out, out);
}